// round 6
// baseline (speedup 1.0000x reference)
#include <cuda_runtime.h>
#include <math.h>

#define NFRAMES 16
#define IMG_H   480
#define IMG_W   640
#define NCH     20
#define PLANE   (IMG_H * IMG_W)
#define DS_H    120
#define DS_W    160
#define NPIX    (DS_H * DS_W)
#define VR      100
#define CELLS   (VR * VR)
#define NSEM    16
#define NOUT    (2 + NSEM)
#define CPC     20          // floats per cell (5 float4 groups)
#define NGRP    5
#define MIN_MAPPED 13
#define MAX_MAPPED 25
#define BCELLS  256         // cells per finalize block
#define BPF     ((CELLS + BCELLS - 1) / BCELLS)   // 40 blocks per frame

// AoS accumulator: per cell 5 float4: [g0..g3]=16 sem sums, [g4]=(obstacle-dilated, explored, pad, pad).
// Statically zero-initialized; finalize restores zeros each launch (invariant).
__device__ float4 g_acc4[NFRAMES * CELLS * NGRP];

__device__ __forceinline__ void red_v4(float4* addr, float a, float b, float c, float d) {
    asm volatile("red.global.add.v4.f32 [%0], {%1, %2, %3, %4};"
                 :: "l"(addr), "f"(a), "f"(b), "f"(c), "f"(d) : "memory");
}

__global__ void scatter_kernel(const float* __restrict__ obs, float f_pix) {
    int idx = blockIdx.x * blockDim.x + threadIdx.x;
    if (idx >= NFRAMES * NPIX) return;
    int f   = idx / NPIX;
    int pix = idx - f * NPIX;
    int row = pix / DS_W;
    int col = pix - row * DS_W;

    const float* base = obs + (size_t)f * NCH * PLANE;
    int poff = (row * 4) * IMG_W + col * 4;

    float depth = __ldg(&base[3 * PLANE + poff]);
    if (!(depth > 20.0f && depth < 500.0f)) return;

    float uu = (float)(col * 4);
    float vv = (float)(row * 4);

    // Bit-exact binning: keep true divides (bin flips would be O(1) errors)
    float X  = __fdiv_rn((uu - 320.0f) * depth, f_pix);
    float Zh = 88.0f + __fdiv_rn((240.0f - vv) * depth, f_pix);

    int xb = __float2int_rn(__fdiv_rn(X, 5.0f) + 50.0f);
    int yb = __float2int_rn(__fdiv_rn(depth, 5.0f));
    int zb = __float2int_rn(__fdiv_rn(Zh, 5.0f)) + 8;

    if (xb < 0 || xb >= VR || yb < 0 || yb >= VR || zb < 0 || zb >= 80) return;

    int cell = yb * VR + xb;
    float* accf = (float*)g_acc4;

    // Batch all 16 semantic plane loads (max MLP) before the atomics
    float s[NSEM];
    #pragma unroll
    for (int c = 0; c < NSEM; c++)
        s[c] = __ldg(&base[(4 + c) * PLANE + poff]);

    // explored indicator: idempotent plain store (group 4, lane .y)
    accf[((size_t)f * CELLS + cell) * CPC + 17] = 1.0f;

    // obstacle: write dilated (3x3, clamped) indicator directly — idempotent (group 4, lane .x)
    if (zb >= MIN_MAPPED && zb < MAX_MAPPED) {
        int y0 = yb > 0 ? yb - 1 : 0, y1 = yb < VR - 1 ? yb + 1 : VR - 1;
        int x0 = xb > 0 ? xb - 1 : 0, x1 = xb < VR - 1 ? xb + 1 : VR - 1;
        for (int yy = y0; yy <= y1; yy++)
            for (int xx = x0; xx <= x1; xx++)
                accf[((size_t)f * CELLS + yy * VR + xx) * CPC + 16] = 1.0f;
    }

    // 16 semantic adds as 4 vector reductions
    float4* c4 = g_acc4 + ((size_t)f * CELLS + cell) * NGRP;
    red_v4(c4 + 0, s[0],  s[1],  s[2],  s[3]);
    red_v4(c4 + 1, s[4],  s[5],  s[6],  s[7]);
    red_v4(c4 + 2, s[8],  s[9],  s[10], s[11]);
    red_v4(c4 + 3, s[12], s[13], s[14], s[15]);
}

// Per-block smem transpose: coalesced AoS loads + fused reset, then per-cell
// conflict-free smem reads and coalesced planar stores.
__global__ void __launch_bounds__(BCELLS) finalize_kernel(float* __restrict__ out) {
    int f     = blockIdx.x / BPF;
    int blk   = blockIdx.x - f * BPF;
    int cell0 = blk * BCELLS;
    int ncell = CELLS - cell0 < BCELLS ? CELLS - cell0 : BCELLS;  // 256 or 16 (tail)
    int t     = threadIdx.x;

    __shared__ float4 sh[NGRP][BCELLS];

    // Load phase: block's acc region is ncell*5 consecutive float4s.
    // Coalesced reads, zeros written straight back (fused reset).
    float4* base = g_acc4 + ((size_t)f * CELLS + cell0) * NGRP;
    const float4 z = make_float4(0.f, 0.f, 0.f, 0.f);
    for (int k = t; k < ncell * NGRP; k += BCELLS) {
        float4 v = base[k];
        base[k] = z;
        int c = k / NGRP;
        int g = k - c * NGRP;
        sh[g][c] = v;
    }
    __syncthreads();

    if (t >= ncell) return;
    int cell = cell0 + t;
    float4 v0 = sh[0][t], v1 = sh[1][t], v2 = sh[2][t], v3 = sh[3][t], v4 = sh[4][t];

    float* dst = out + (size_t)f * NOUT * CELLS + cell;
    dst[0]     = v4.x;   // obstacle (already dilated, {0,1})
    dst[CELLS] = v4.y;   // explored (EXP_T=1 -> identity)

    float sv[NSEM] = {v0.x,v0.y,v0.z,v0.w, v1.x,v1.y,v1.z,v1.w,
                      v2.x,v2.y,v2.z,v2.w, v3.x,v3.y,v3.z,v3.w};
    float* d = dst + 2 * CELLS;
    #pragma unroll
    for (int c = 0; c < NSEM; c++) {
        // x*0.2f differs from x/5 by <=1 ULP; output-only, far under 1e-3 tol
        d[0] = fminf(fmaxf(__fmul_rn(sv[c], 0.2f), 0.0f), 1.0f);
        d += CELLS;
    }
}

extern "C" void kernel_launch(void* const* d_in, const int* in_sizes, int n_in,
                              void* d_out, int out_size) {
    const float* obs = (const float*)d_in[0];   // (4,4,20,480,640) f32
    float* out = (float*)d_out;                 // (4,4,18,100,100) f32

    float f_pix = (float)(320.0 / tan(39.5 * 3.14159265358979323846 / 180.0));

    scatter_kernel<<<(NFRAMES * NPIX + 255) / 256, 256>>>(obs, f_pix);
    finalize_kernel<<<NFRAMES * BPF, BCELLS>>>(out);
}

// round 7
// speedup vs baseline: 1.2678x; 1.2678x over previous
#include <cuda_runtime.h>
#include <math.h>

#define NFRAMES 16
#define IMG_H   480
#define IMG_W   640
#define NCH     20
#define PLANE   (IMG_H * IMG_W)
#define DS_H    120
#define DS_W    160
#define NPIX    (DS_H * DS_W)
#define VR      100
#define CELLS   (VR * VR)
#define NSEM    16
#define NOUT    (2 + NSEM)
#define MIN_MAPPED 13
#define MAX_MAPPED 25

// Planar-by-group accumulators. Statically zero-initialized; finalize restores
// zeros each launch (invariant: acc is all-zero on entry to kernel_launch).
// g_sem[f][g][cell] : float4 = semantic channels 4g..4g+3 summed for that cell.
__device__ float4 g_sem[NFRAMES][4][CELLS];
// g_ind[f][0][cell] = dilated obstacle indicator, g_ind[f][1][cell] = explored indicator.
__device__ float  g_ind[NFRAMES][2][CELLS];

__device__ __forceinline__ void red_v4(float4* addr, float a, float b, float c, float d) {
    asm volatile("red.global.add.v4.f32 [%0], {%1, %2, %3, %4};"
                 :: "l"(addr), "f"(a), "f"(b), "f"(c), "f"(d) : "memory");
}

__global__ void scatter_kernel(const float* __restrict__ obs, float f_pix) {
    int idx = blockIdx.x * blockDim.x + threadIdx.x;
    if (idx >= NFRAMES * NPIX) return;
    int f   = idx / NPIX;
    int pix = idx - f * NPIX;
    int row = pix / DS_W;
    int col = pix - row * DS_W;

    const float* base = obs + (size_t)f * NCH * PLANE;
    int poff = (row * 4) * IMG_W + col * 4;

    float depth = __ldg(&base[3 * PLANE + poff]);
    if (!(depth > 20.0f && depth < 500.0f)) return;

    float uu = (float)(col * 4);
    float vv = (float)(row * 4);

    // Bit-exact binning: keep true divides (bin flips would be O(1) errors)
    float X  = __fdiv_rn((uu - 320.0f) * depth, f_pix);
    float Zh = 88.0f + __fdiv_rn((240.0f - vv) * depth, f_pix);

    int xb = __float2int_rn(__fdiv_rn(X, 5.0f) + 50.0f);
    int yb = __float2int_rn(__fdiv_rn(depth, 5.0f));
    int zb = __float2int_rn(__fdiv_rn(Zh, 5.0f)) + 8;

    if (xb < 0 || xb >= VR || yb < 0 || yb >= VR || zb < 0 || zb >= 80) return;

    int cell = yb * VR + xb;

    // Batch all 16 semantic plane loads (max MLP) before the atomics
    float s[NSEM];
    #pragma unroll
    for (int c = 0; c < NSEM; c++)
        s[c] = __ldg(&base[(4 + c) * PLANE + poff]);

    // explored indicator: idempotent plain store
    g_ind[f][1][cell] = 1.0f;

    // obstacle: write dilated (3x3, clamped) indicator directly — idempotent.
    // Planar layout: 3 consecutive floats per row -> 3 sectors max.
    if (zb >= MIN_MAPPED && zb < MAX_MAPPED) {
        int y0 = yb > 0 ? yb - 1 : 0, y1 = yb < VR - 1 ? yb + 1 : VR - 1;
        int x0 = xb > 0 ? xb - 1 : 0, x1 = xb < VR - 1 ? xb + 1 : VR - 1;
        for (int yy = y0; yy <= y1; yy++)
            for (int xx = x0; xx <= x1; xx++)
                g_ind[f][0][yy * VR + xx] = 1.0f;
    }

    // 16 semantic adds as 4 vector reductions into 4 planar float4 planes
    red_v4(&g_sem[f][0][cell], s[0],  s[1],  s[2],  s[3]);
    red_v4(&g_sem[f][1][cell], s[4],  s[5],  s[6],  s[7]);
    red_v4(&g_sem[f][2][cell], s[8],  s[9],  s[10], s[11]);
    red_v4(&g_sem[f][3][cell], s[12], s[13], s[14], s[15]);
}

// Thread per cell; all loads and stores lane-coalesced in the planar layout.
__global__ void __launch_bounds__(256) finalize_kernel(float* __restrict__ out) {
    int idx = blockIdx.x * blockDim.x + threadIdx.x;
    if (idx >= NFRAMES * CELLS) return;
    int f    = idx / CELLS;
    int cell = idx - f * CELLS;

    // Coalesced: consecutive lanes -> consecutive 16B (LDG.128) / 4B (LDG.32)
    float4 v0 = g_sem[f][0][cell];
    float4 v1 = g_sem[f][1][cell];
    float4 v2 = g_sem[f][2][cell];
    float4 v3 = g_sem[f][3][cell];
    float  ob = g_ind[f][0][cell];
    float  ex = g_ind[f][1][cell];

    // Fused reset (own addresses only -> race-free, coalesced)
    const float4 z = make_float4(0.f, 0.f, 0.f, 0.f);
    g_sem[f][0][cell] = z;
    g_sem[f][1][cell] = z;
    g_sem[f][2][cell] = z;
    g_sem[f][3][cell] = z;
    g_ind[f][0][cell] = 0.0f;
    g_ind[f][1][cell] = 0.0f;

    float* dst = out + (size_t)f * NOUT * CELLS + cell;
    dst[0]     = ob;   // obstacle (already dilated, {0,1})
    dst[CELLS] = ex;   // explored (EXP_T=1 -> identity)

    float sv[NSEM] = {v0.x,v0.y,v0.z,v0.w, v1.x,v1.y,v1.z,v1.w,
                      v2.x,v2.y,v2.z,v2.w, v3.x,v3.y,v3.z,v3.w};
    float* d = dst + 2 * CELLS;
    #pragma unroll
    for (int c = 0; c < NSEM; c++) {
        // x*0.2f differs from x/5 by <=1 ULP; output-only, far under 1e-3 tol
        d[0] = fminf(fmaxf(__fmul_rn(sv[c], 0.2f), 0.0f), 1.0f);
        d += CELLS;
    }
}

extern "C" void kernel_launch(void* const* d_in, const int* in_sizes, int n_in,
                              void* d_out, int out_size) {
    const float* obs = (const float*)d_in[0];   // (4,4,20,480,640) f32
    float* out = (float*)d_out;                 // (4,4,18,100,100) f32

    float f_pix = (float)(320.0 / tan(39.5 * 3.14159265358979323846 / 180.0));

    scatter_kernel<<<(NFRAMES * NPIX + 255) / 256, 256>>>(obs, f_pix);
    finalize_kernel<<<(NFRAMES * CELLS + 255) / 256, 256>>>(out);
}